// round 4
// baseline (speedup 1.0000x reference)
#include <cuda_runtime.h>
#include <math.h>

#define T_DIM 32
#define B_DIM 16
#define S_DIM 128
#define D_DIM 1024

// Scratch (device globals: allocation-free per harness rules)
__device__ float g_pi[T_DIM * B_DIM * D_DIM];      // 2 MB  [T,B,D]
__device__ float g_pc[B_DIM * S_DIM * D_DIM];      // 8 MB  [B,S,D]
__device__ float g_scores[T_DIM * B_DIM * S_DIM];  // 256 KB [T,B,S]

// ---------------------------------------------------------------------------
// Fused dual GEMM (NT): C[m,n] = sum_k A[m,k] * W[n,k] + bias[n]
//   blocks [0,64):    pi  = inputs  @ W_in^T  + b_in   (M=512)
//   blocks [64,320):  pc  = context @ W_ctx^T + b_ctx  (M=2048)
// BM=64, BN=128, BK=16, 256 threads, 4x8 per-thread tile, double-buffered.
// ---------------------------------------------------------------------------
#define BM 64
#define BN 128
#define BK 16
#define PI_BLOCKS 64            // (512/BM) * (1024/BN) = 8*8
#define PC_BLOCKS 256           // (2048/BM) * (1024/BN) = 32*8

__global__ __launch_bounds__(256, 3)
void gemm_both(const float* __restrict__ inputs, const float* __restrict__ W_in,
               const float* __restrict__ b_in,
               const float* __restrict__ context, const float* __restrict__ W_ctx,
               const float* __restrict__ b_ctx)
{
    __shared__ float As[2][BK][BM + 4];
    __shared__ float Bs[2][BK][BN + 4];

    const int bid = blockIdx.x;
    const float* A; const float* W; const float* bias; float* C;
    int bm, bn;
    if (bid < PI_BLOCKS) {
        A = inputs;  W = W_in;  bias = b_in;  C = g_pi;
        bm = (bid >> 3) * BM;  bn = (bid & 7) * BN;
    } else {
        const int b2 = bid - PI_BLOCKS;
        A = context; W = W_ctx; bias = b_ctx; C = g_pc;
        bm = (b2 >> 3) * BM;   bn = (b2 & 7) * BN;
    }
    const int K = D_DIM, N = D_DIM;

    const int tid = threadIdx.x;              // 256 threads
    // A tile: 64 rows x 16 k = 256 float4, 1 per thread
    const int arow = tid >> 2, akq = (tid & 3) << 2;
    // B tile: 128 rows x 16 k = 512 float4, 2 per thread
    const int brow0 = tid >> 2,         bkq0 = (tid & 3) << 2;
    const int brow1 = (tid + 256) >> 2, bkq1 = ((tid + 256) & 3) << 2;

    // Compute mapping: 16 row-groups x 16 col-groups
    const int trow = (tid >> 4) * 4;          // 0..60
    const int tcol = (tid & 15) * 8;          // 0..120

    float acc[4][8];
    #pragma unroll
    for (int i = 0; i < 4; i++)
        #pragma unroll
        for (int j = 0; j < 8; j++) acc[i][j] = 0.f;

    // Prologue: tile 0 -> buffer 0
    {
        float4 va  = *(const float4*)(A + (size_t)(bm + arow)  * K + akq);
        float4 vb0 = *(const float4*)(W + (size_t)(bn + brow0) * K + bkq0);
        float4 vb1 = *(const float4*)(W + (size_t)(bn + brow1) * K + bkq1);
        As[0][akq + 0][arow]  = va.x;  As[0][akq + 1][arow]  = va.y;
        As[0][akq + 2][arow]  = va.z;  As[0][akq + 3][arow]  = va.w;
        Bs[0][bkq0 + 0][brow0] = vb0.x; Bs[0][bkq0 + 1][brow0] = vb0.y;
        Bs[0][bkq0 + 2][brow0] = vb0.z; Bs[0][bkq0 + 3][brow0] = vb0.w;
        Bs[0][bkq1 + 0][brow1] = vb1.x; Bs[0][bkq1 + 1][brow1] = vb1.y;
        Bs[0][bkq1 + 2][brow1] = vb1.z; Bs[0][bkq1 + 3][brow1] = vb1.w;
    }
    __syncthreads();

    for (int k0 = 0; k0 < K; k0 += BK) {
        const int cur = (k0 / BK) & 1;
        const int nxt = cur ^ 1;

        if (k0 + BK < K) {
            const int kn = k0 + BK;
            float4 va  = *(const float4*)(A + (size_t)(bm + arow)  * K + kn + akq);
            float4 vb0 = *(const float4*)(W + (size_t)(bn + brow0) * K + kn + bkq0);
            float4 vb1 = *(const float4*)(W + (size_t)(bn + brow1) * K + kn + bkq1);
            As[nxt][akq + 0][arow]  = va.x;  As[nxt][akq + 1][arow]  = va.y;
            As[nxt][akq + 2][arow]  = va.z;  As[nxt][akq + 3][arow]  = va.w;
            Bs[nxt][bkq0 + 0][brow0] = vb0.x; Bs[nxt][bkq0 + 1][brow0] = vb0.y;
            Bs[nxt][bkq0 + 2][brow0] = vb0.z; Bs[nxt][bkq0 + 3][brow0] = vb0.w;
            Bs[nxt][bkq1 + 0][brow1] = vb1.x; Bs[nxt][bkq1 + 1][brow1] = vb1.y;
            Bs[nxt][bkq1 + 2][brow1] = vb1.z; Bs[nxt][bkq1 + 3][brow1] = vb1.w;
        }

        #pragma unroll
        for (int kk = 0; kk < BK; kk++) {
            float a[4], b[8];
            #pragma unroll
            for (int i = 0; i < 4; i++) a[i] = As[cur][kk][trow + i];
            #pragma unroll
            for (int j = 0; j < 8; j++) b[j] = Bs[cur][kk][tcol + j];
            #pragma unroll
            for (int i = 0; i < 4; i++)
                #pragma unroll
                for (int j = 0; j < 8; j++)
                    acc[i][j] = fmaf(a[i], b[j], acc[i][j]);
        }
        __syncthreads();
    }

    // Epilogue: bias preloaded as float4, vectorized 128-bit stores
    {
        float4 bv0 = *(const float4*)(bias + bn + tcol);
        float4 bv1 = *(const float4*)(bias + bn + tcol + 4);
        #pragma unroll
        for (int i = 0; i < 4; i++) {
            float4 o0, o1;
            o0.x = acc[i][0] + bv0.x; o0.y = acc[i][1] + bv0.y;
            o0.z = acc[i][2] + bv0.z; o0.w = acc[i][3] + bv0.w;
            o1.x = acc[i][4] + bv1.x; o1.y = acc[i][5] + bv1.y;
            o1.z = acc[i][6] + bv1.z; o1.w = acc[i][7] + bv1.w;
            float* dst = C + (size_t)(bm + trow + i) * N + bn + tcol;
            *(float4*)(dst)     = o0;
            *(float4*)(dst + 4) = o1;
        }
    }
}

// ---------------------------------------------------------------------------
// scores[t,b,s] = sum_d swish(pi[t,b,d] + pc[b,s,d]) * w_one[d]
// Block: one b, 16 t's, 32 s's. Loop over d in chunks of 128.
// Each thread: 1 t x 2 s (s and s+16).
// ---------------------------------------------------------------------------
#define TT 16
#define SB 32
#define DC 128

__global__ __launch_bounds__(256)
void scores_kernel(const float* __restrict__ w_one)
{
    __shared__ float sp[TT][DC + 1];   // padded: avoid bank conflicts
    __shared__ float sc[SB][DC + 1];
    __shared__ float sw[DC];

    const int b   = blockIdx.z;
    const int t0  = blockIdx.y * TT;
    const int s0  = blockIdx.x * SB;
    const int tid = threadIdx.x;
    const int tl  = tid >> 4;          // 0..15 (t within tile)
    const int sl  = tid & 15;          // 0..15 (s within half-tile)

    float acc0 = 0.f, acc1 = 0.f;

    for (int d0 = 0; d0 < D_DIM; d0 += DC) {
        // pi tile: 16 rows x 128 = 512 float4, 2 per thread
        #pragma unroll
        for (int i = 0; i < 2; i++) {
            int l = tid + i * 256;
            int row = l >> 5;                  // 0..15
            int c = (l & 31) << 2;             // 0..124
            float4 v = *(const float4*)(g_pi +
                ((size_t)(t0 + row) * B_DIM + b) * D_DIM + d0 + c);
            sp[row][c] = v.x; sp[row][c + 1] = v.y;
            sp[row][c + 2] = v.z; sp[row][c + 3] = v.w;
        }
        // pc tile: 32 rows x 128 = 1024 float4, 4 per thread
        #pragma unroll
        for (int i = 0; i < 4; i++) {
            int l = tid + i * 256;
            int row = l >> 5;                  // 0..31
            int c = (l & 31) << 2;
            float4 v = *(const float4*)(g_pc +
                ((size_t)b * S_DIM + s0 + row) * D_DIM + d0 + c);
            sc[row][c] = v.x; sc[row][c + 1] = v.y;
            sc[row][c + 2] = v.z; sc[row][c + 3] = v.w;
        }
        if (tid < DC) sw[tid] = w_one[d0 + tid];
        __syncthreads();

        #pragma unroll 8
        for (int k = 0; k < DC; k++) {
            float w = sw[k];
            float p = sp[tl][k];
            float x0 = p + sc[sl][k];
            float x1 = p + sc[sl + 16][k];
            float g0 = __fdividef(1.f, 1.f + __expf(-x0));
            float g1 = __fdividef(1.f, 1.f + __expf(-x1));
            acc0 = fmaf(w * x0, g0, acc0);
            acc1 = fmaf(w * x1, g1, acc1);
        }
        __syncthreads();
    }

    g_scores[((size_t)(t0 + tl) * B_DIM + b) * S_DIM + s0 + sl]      = acc0;
    g_scores[((size_t)(t0 + tl) * B_DIM + b) * S_DIM + s0 + sl + 16] = acc1;
}

// ---------------------------------------------------------------------------
// Softmax over s + attn_context[t,b,d] = sum_s attn[t,b,s] * context[b,s,d]
// Block: one (b, d-chunk of 128). All 32 t's handled in-block.
// ---------------------------------------------------------------------------
__global__ __launch_bounds__(256)
void softmax_av_kernel(const float* __restrict__ context,
                       float* __restrict__ out_ctx,
                       float* __restrict__ out_attn)
{
    __shared__ float sat[T_DIM][S_DIM];   // 16 KB: attn (in place over scores)
    __shared__ float sctx[64][128];       // 32 KB: context chunk [s, d]

    const int dc  = blockIdx.x;           // 0..7 (d-chunk)
    const int b   = blockIdx.y;
    const int tid = threadIdx.x;

    // 1) Load scores [32,128] for this b
    #pragma unroll
    for (int i = 0; i < 16; i++) {
        int l = tid + i * 256;
        int t = l >> 7;
        int s = l & 127;
        sat[t][s] = g_scores[((size_t)t * B_DIM + b) * S_DIM + s];
    }
    __syncthreads();

    // 2) Softmax per t-row: 8 threads per row, 16 s each, shfl reduce (width 8)
    {
        int t = tid >> 3;
        int part = tid & 7;
        int sbase = part * 16;
        float m = -1e30f;
        #pragma unroll
        for (int i = 0; i < 16; i++) m = fmaxf(m, sat[t][sbase + i]);
        #pragma unroll
        for (int o = 4; o > 0; o >>= 1)
            m = fmaxf(m, __shfl_xor_sync(0xffffffffu, m, o, 8));
        float e[16];
        float sum = 0.f;
        #pragma unroll
        for (int i = 0; i < 16; i++) {
            e[i] = __expf(sat[t][sbase + i] - m);
            sum += e[i];
        }
        #pragma unroll
        for (int o = 4; o > 0; o >>= 1)
            sum += __shfl_xor_sync(0xffffffffu, sum, o, 8);
        float inv = __fdividef(1.f, sum);
        #pragma unroll
        for (int i = 0; i < 16; i++) sat[t][sbase + i] = e[i] * inv;
    }
    __syncthreads();

    // 3) Write attn output (only the dc==0 block per b)
    if (dc == 0) {
        int t = tid >> 3;
        int sbase = (tid & 7) * 16;
        #pragma unroll
        for (int i = 0; i < 16; i++)
            out_attn[((size_t)t * B_DIM + b) * S_DIM + sbase + i] = sat[t][sbase + i];
    }

    // 4) AV: each thread owns (t2 in {0,1} interleaved over 32 t's, one d lane)
    const int t2 = tid >> 7;        // 0..1
    const int dl = tid & 127;       // 0..127
    float acc[16];
    #pragma unroll
    for (int i = 0; i < 16; i++) acc[i] = 0.f;

    for (int sc0 = 0; sc0 < S_DIM; sc0 += 64) {
        __syncthreads();   // protect sctx reuse (and attn-write above on iter 0)
        #pragma unroll
        for (int i = 0; i < 8; i++) {
            int l = tid + i * 256;             // 2048 float4
            int row = l >> 5;                  // 0..63
            int c = (l & 31) << 2;
            float4 v = *(const float4*)(context +
                ((size_t)b * S_DIM + sc0 + row) * D_DIM + dc * 128 + c);
            sctx[row][c] = v.x; sctx[row][c + 1] = v.y;
            sctx[row][c + 2] = v.z; sctx[row][c + 3] = v.w;
        }
        __syncthreads();

        for (int s = 0; s < 64; s++) {
            float cv = sctx[s][dl];
            #pragma unroll
            for (int i = 0; i < 16; i++)
                acc[i] = fmaf(sat[i * 2 + t2][sc0 + s], cv, acc[i]);
        }
    }

    #pragma unroll
    for (int i = 0; i < 16; i++) {
        out_ctx[((size_t)(i * 2 + t2) * B_DIM + b) * D_DIM + dc * 128 + dl] = acc[i];
    }
}

// ---------------------------------------------------------------------------
// Launch
// Inputs (metadata order): inputs, context, W_in, b_in, W_ctx, b_ctx, w_one, b_one
// Output: attn_context [T,B,D] then attn [T,B,S] (concatenated, fp32)
// b_one is a scalar shift on scores -> softmax is shift-invariant and scores
// are not returned, so it provably cannot affect either output. Skipped.
// ---------------------------------------------------------------------------
extern "C" void kernel_launch(void* const* d_in, const int* in_sizes, int n_in,
                              void* d_out, int out_size)
{
    const float* inputs  = (const float*)d_in[0];
    const float* context = (const float*)d_in[1];
    const float* W_in    = (const float*)d_in[2];
    const float* b_in    = (const float*)d_in[3];
    const float* W_ctx   = (const float*)d_in[4];
    const float* b_ctx   = (const float*)d_in[5];
    const float* w_one   = (const float*)d_in[6];

    float* out      = (float*)d_out;
    float* out_ctx  = out;                                   // [T,B,D]
    float* out_attn = out + (size_t)T_DIM * B_DIM * D_DIM;   // [T,B,S]

    // Fused pi + pc GEMMs: 64 + 256 = 320 blocks in one launch
    gemm_both<<<PI_BLOCKS + PC_BLOCKS, 256>>>(inputs, W_in, b_in,
                                              context, W_ctx, b_ctx);
    // scores
    {
        dim3 grid(S_DIM / SB, T_DIM / TT, B_DIM);            // (4, 2, 16) = 128 blocks
        scores_kernel<<<grid, 256>>>(w_one);
    }
    // softmax + AV
    {
        dim3 grid(D_DIM / 128, B_DIM);                       // (8, 16) = 128 blocks
        softmax_av_kernel<<<grid, 256>>>(context, out_ctx, out_attn);
    }
}

// round 7
// speedup vs baseline: 2.0731x; 2.0731x over previous
#include <cuda_runtime.h>
#include <math.h>

#define T_DIM 32
#define B_DIM 16
#define S_DIM 128
#define D_DIM 1024

// Scratch (device globals: allocation-free per harness rules)
__device__ float g_pi[T_DIM * B_DIM * D_DIM];      // 2 MB  [T,B,D]
__device__ float g_pc[B_DIM * S_DIM * D_DIM];      // 8 MB  [B,S,D]
__device__ float g_scores[T_DIM * B_DIM * S_DIM];  // 256 KB [T,B,S]

// ===========================================================================
// Tensor-core GEMM (NT): C[m,n] = sum_k A[m,k]*W[n,k] + bias[n]
// mma.sync.m16n8k8 tf32 with 3-term split (Ah*Bh + Ah*Bl + Al*Bh) ~= fp32.
// Block tile 64x64, BK=32, 128 threads (4 warps, each 32x32), cp.async
// 2-stage pipeline. Blocks [0,128): pi (M=512). Blocks [128,640): pc (M=2048).
// ===========================================================================
#define GBM 64
#define GBN 64
#define GBK 32
#define GKPAD 36                 // 32 + 4 floats: 16B-aligned rows, no LDS conflicts
#define PI_BLOCKS 128            // (512/64) * (1024/64)
#define PC_BLOCKS 512            // (2048/64) * (1024/64)
#define NKT (D_DIM / GBK)        // 32 k-tiles

__device__ __forceinline__ void cp16(void* smem, const void* g) {
    unsigned saddr = (unsigned)__cvta_generic_to_shared(smem);
    asm volatile("cp.async.cg.shared.global [%0], [%1], 16;" :: "r"(saddr), "l"(g));
}
__device__ __forceinline__ void split_tf32(float f, unsigned& hi, unsigned& lo) {
    asm("cvt.rna.tf32.f32 %0, %1;" : "=r"(hi) : "f"(f));
    float r = f - __uint_as_float(hi);
    asm("cvt.rna.tf32.f32 %0, %1;" : "=r"(lo) : "f"(r));
}
__device__ __forceinline__ void mma_tf32(float c[4], const unsigned a[4], const unsigned b[2]) {
    asm volatile(
        "mma.sync.aligned.m16n8k8.row.col.f32.tf32.tf32.f32 "
        "{%0,%1,%2,%3}, {%4,%5,%6,%7}, {%8,%9}, {%0,%1,%2,%3};"
        : "+f"(c[0]), "+f"(c[1]), "+f"(c[2]), "+f"(c[3])
        : "r"(a[0]), "r"(a[1]), "r"(a[2]), "r"(a[3]), "r"(b[0]), "r"(b[1]));
}

__global__ __launch_bounds__(128, 4)
void gemm_tc(const float* __restrict__ inputs, const float* __restrict__ W_in,
             const float* __restrict__ b_in,
             const float* __restrict__ context, const float* __restrict__ W_ctx,
             const float* __restrict__ b_ctx)
{
    __shared__ __align__(16) float As[2][GBM][GKPAD];
    __shared__ __align__(16) float Bs[2][GBN][GKPAD];

    const int bid = blockIdx.x;
    const float* A; const float* W; const float* bias; float* C;
    int bm, bn;
    if (bid < PI_BLOCKS) {
        A = inputs;  W = W_in;  bias = b_in;  C = g_pi;
        bm = (bid >> 4) * GBM;  bn = (bid & 15) * GBN;
    } else {
        const int b2 = bid - PI_BLOCKS;
        A = context; W = W_ctx; bias = b_ctx; C = g_pc;
        bm = (b2 >> 4) * GBM;   bn = (b2 & 15) * GBN;
    }
    const int K = D_DIM, N = D_DIM;

    const int tid  = threadIdx.x;          // 128
    const int wid  = tid >> 5;             // 0..3
    const int lane = tid & 31;
    const int warp_m = (wid & 1) * 32;
    const int warp_n = (wid >> 1) * 32;
    const int lr = lane >> 2;              // 0..7
    const int lc = lane & 3;               // 0..3

    float acc[2][4][4];
    #pragma unroll
    for (int i = 0; i < 2; i++)
        #pragma unroll
        for (int j = 0; j < 4; j++)
            #pragma unroll
            for (int q = 0; q < 4; q++) acc[i][j][q] = 0.f;

    // --- async tile loader: 512 16B chunks per operand, 4 per thread each ---
    auto issue = [&](int kt, int buf) {
        const int k0 = kt * GBK;
        #pragma unroll
        for (int i = 0; i < 4; i++) {
            int id  = tid + i * 128;       // 0..511
            int row = id >> 3;             // 0..63
            int c4  = (id & 7) * 4;        // float offset, 16B chunks
            cp16(&As[buf][row][c4], A + (size_t)(bm + row) * K + k0 + c4);
            cp16(&Bs[buf][row][c4], W + (size_t)(bn + row) * K + k0 + c4);
        }
        asm volatile("cp.async.commit_group;");
    };

    issue(0, 0);
    issue(1, 1);

    for (int kt = 0; kt < NKT; kt++) {
        if (kt < NKT - 1) asm volatile("cp.async.wait_group 1;");
        else              asm volatile("cp.async.wait_group 0;");
        __syncthreads();

        const int st = kt & 1;
        #pragma unroll
        for (int ka = 0; ka < 4; ka++) {
            const int k8 = ka * 8;
            // A fragments (2 m-atoms), split hi/lo
            unsigned ah[2][4], al[2][4];
            #pragma unroll
            for (int i = 0; i < 2; i++) {
                int r = warp_m + i * 16 + lr;
                split_tf32(As[st][r][k8 + lc],         ah[i][0], al[i][0]);
                split_tf32(As[st][r + 8][k8 + lc],     ah[i][1], al[i][1]);
                split_tf32(As[st][r][k8 + lc + 4],     ah[i][2], al[i][2]);
                split_tf32(As[st][r + 8][k8 + lc + 4], ah[i][3], al[i][3]);
            }
            // B fragments (4 n-atoms), split hi/lo
            unsigned bh[4][2], bl[4][2];
            #pragma unroll
            for (int j = 0; j < 4; j++) {
                int n = warp_n + j * 8 + lr;
                split_tf32(Bs[st][n][k8 + lc],     bh[j][0], bl[j][0]);
                split_tf32(Bs[st][n][k8 + lc + 4], bh[j][1], bl[j][1]);
            }
            #pragma unroll
            for (int i = 0; i < 2; i++)
                #pragma unroll
                for (int j = 0; j < 4; j++) {
                    mma_tf32(acc[i][j], ah[i], bh[j]);   // main
                    mma_tf32(acc[i][j], ah[i], bl[j]);   // A_hi * B_lo
                    mma_tf32(acc[i][j], al[i], bh[j]);   // A_lo * B_hi
                }
        }
        __syncthreads();
        if (kt + 2 < NKT) issue(kt + 2, st);
    }

    // Epilogue: c0/c1 at (row, 2c),(row, 2c+1); c2/c3 at row+8. float2 stores.
    #pragma unroll
    for (int i = 0; i < 2; i++) {
        int r0 = bm + warp_m + i * 16 + lr;
        #pragma unroll
        for (int j = 0; j < 4; j++) {
            int c0 = bn + warp_n + j * 8 + 2 * lc;
            float2 bv = *(const float2*)(bias + c0);
            float2 o0 = make_float2(acc[i][j][0] + bv.x, acc[i][j][1] + bv.y);
            float2 o1 = make_float2(acc[i][j][2] + bv.x, acc[i][j][3] + bv.y);
            *(float2*)(C + (size_t)r0 * N + c0)       = o0;
            *(float2*)(C + (size_t)(r0 + 8) * N + c0) = o1;
        }
    }
}

// ---------------------------------------------------------------------------
// scores[t,b,s] = sum_d swish(pi[t,b,d] + pc[b,s,d]) * w_one[d]
// sigmoid via MUFU.TANH: sigmoid(x) = 0.5*tanh(x/2) + 0.5  (1 MUFU vs 2)
// ---------------------------------------------------------------------------
#define TT 16
#define SB 32
#define DC 128

__device__ __forceinline__ float fast_sigmoid(float x) {
    float h = 0.5f * x, t;
    asm("tanh.approx.f32 %0, %1;" : "=f"(t) : "f"(h));
    return fmaf(0.5f, t, 0.5f);
}

__global__ __launch_bounds__(256)
void scores_kernel(const float* __restrict__ w_one)
{
    __shared__ float sp[TT][DC + 1];
    __shared__ float sc[SB][DC + 1];
    __shared__ float sw[DC];

    const int b   = blockIdx.z;
    const int t0  = blockIdx.y * TT;
    const int s0  = blockIdx.x * SB;
    const int tid = threadIdx.x;
    const int tl  = tid >> 4;
    const int sl  = tid & 15;

    float acc0 = 0.f, acc1 = 0.f;

    for (int d0 = 0; d0 < D_DIM; d0 += DC) {
        #pragma unroll
        for (int i = 0; i < 2; i++) {
            int l = tid + i * 256;
            int row = l >> 5;
            int c = (l & 31) << 2;
            float4 v = *(const float4*)(g_pi +
                ((size_t)(t0 + row) * B_DIM + b) * D_DIM + d0 + c);
            sp[row][c] = v.x; sp[row][c + 1] = v.y;
            sp[row][c + 2] = v.z; sp[row][c + 3] = v.w;
        }
        #pragma unroll
        for (int i = 0; i < 4; i++) {
            int l = tid + i * 256;
            int row = l >> 5;
            int c = (l & 31) << 2;
            float4 v = *(const float4*)(g_pc +
                ((size_t)b * S_DIM + s0 + row) * D_DIM + d0 + c);
            sc[row][c] = v.x; sc[row][c + 1] = v.y;
            sc[row][c + 2] = v.z; sc[row][c + 3] = v.w;
        }
        if (tid < DC) sw[tid] = w_one[d0 + tid];
        __syncthreads();

        #pragma unroll 8
        for (int k = 0; k < DC; k++) {
            float w = sw[k];
            float p = sp[tl][k];
            float x0 = p + sc[sl][k];
            float x1 = p + sc[sl + 16][k];
            acc0 = fmaf(w * x0, fast_sigmoid(x0), acc0);
            acc1 = fmaf(w * x1, fast_sigmoid(x1), acc1);
        }
        __syncthreads();
    }

    g_scores[((size_t)(t0 + tl) * B_DIM + b) * S_DIM + s0 + sl]      = acc0;
    g_scores[((size_t)(t0 + tl) * B_DIM + b) * S_DIM + s0 + sl + 16] = acc1;
}

// ---------------------------------------------------------------------------
// Softmax over s + attn_context[t,b,d] = sum_s attn[t,b,s] * context[b,s,d]
// ---------------------------------------------------------------------------
__global__ __launch_bounds__(256)
void softmax_av_kernel(const float* __restrict__ context,
                       float* __restrict__ out_ctx,
                       float* __restrict__ out_attn)
{
    __shared__ float sat[T_DIM][S_DIM];
    __shared__ float sctx[64][128];

    const int dc  = blockIdx.x;
    const int b   = blockIdx.y;
    const int tid = threadIdx.x;

    #pragma unroll
    for (int i = 0; i < 16; i++) {
        int l = tid + i * 256;
        int t = l >> 7;
        int s = l & 127;
        sat[t][s] = g_scores[((size_t)t * B_DIM + b) * S_DIM + s];
    }
    __syncthreads();

    {
        int t = tid >> 3;
        int part = tid & 7;
        int sbase = part * 16;
        float m = -1e30f;
        #pragma unroll
        for (int i = 0; i < 16; i++) m = fmaxf(m, sat[t][sbase + i]);
        #pragma unroll
        for (int o = 4; o > 0; o >>= 1)
            m = fmaxf(m, __shfl_xor_sync(0xffffffffu, m, o, 8));
        float e[16];
        float sum = 0.f;
        #pragma unroll
        for (int i = 0; i < 16; i++) {
            e[i] = __expf(sat[t][sbase + i] - m);
            sum += e[i];
        }
        #pragma unroll
        for (int o = 4; o > 0; o >>= 1)
            sum += __shfl_xor_sync(0xffffffffu, sum, o, 8);
        float inv = __fdividef(1.f, sum);
        #pragma unroll
        for (int i = 0; i < 16; i++) sat[t][sbase + i] = e[i] * inv;
    }
    __syncthreads();

    if (dc == 0) {
        int t = tid >> 3;
        int sbase = (tid & 7) * 16;
        #pragma unroll
        for (int i = 0; i < 16; i++)
            out_attn[((size_t)t * B_DIM + b) * S_DIM + sbase + i] = sat[t][sbase + i];
    }

    const int t2 = tid >> 7;
    const int dl = tid & 127;
    float acc[16];
    #pragma unroll
    for (int i = 0; i < 16; i++) acc[i] = 0.f;

    for (int sc0 = 0; sc0 < S_DIM; sc0 += 64) {
        __syncthreads();
        #pragma unroll
        for (int i = 0; i < 8; i++) {
            int l = tid + i * 256;
            int row = l >> 5;
            int c = (l & 31) << 2;
            float4 v = *(const float4*)(context +
                ((size_t)b * S_DIM + sc0 + row) * D_DIM + dc * 128 + c);
            sctx[row][c] = v.x; sctx[row][c + 1] = v.y;
            sctx[row][c + 2] = v.z; sctx[row][c + 3] = v.w;
        }
        __syncthreads();

        for (int s = 0; s < 64; s++) {
            float cv = sctx[s][dl];
            #pragma unroll
            for (int i = 0; i < 16; i++)
                acc[i] = fmaf(sat[i * 2 + t2][sc0 + s], cv, acc[i]);
        }
    }

    #pragma unroll
    for (int i = 0; i < 16; i++) {
        out_ctx[((size_t)(i * 2 + t2) * B_DIM + b) * D_DIM + dc * 128 + dl] = acc[i];
    }
}

// ---------------------------------------------------------------------------
// Launch.  b_one skipped (softmax shift-invariant; scores not an output).
// ---------------------------------------------------------------------------
extern "C" void kernel_launch(void* const* d_in, const int* in_sizes, int n_in,
                              void* d_out, int out_size)
{
    const float* inputs  = (const float*)d_in[0];
    const float* context = (const float*)d_in[1];
    const float* W_in    = (const float*)d_in[2];
    const float* b_in    = (const float*)d_in[3];
    const float* W_ctx   = (const float*)d_in[4];
    const float* b_ctx   = (const float*)d_in[5];
    const float* w_one   = (const float*)d_in[6];

    float* out      = (float*)d_out;
    float* out_ctx  = out;                                   // [T,B,D]
    float* out_attn = out + (size_t)T_DIM * B_DIM * D_DIM;   // [T,B,S]

    // Fused pi + pc tensor-core GEMMs: 128 + 512 = 640 blocks
    gemm_tc<<<PI_BLOCKS + PC_BLOCKS, 128>>>(inputs, W_in, b_in,
                                            context, W_ctx, b_ctx);
    // scores
    {
        dim3 grid(S_DIM / SB, T_DIM / TT, B_DIM);            // 128 blocks
        scores_kernel<<<grid, 256>>>(w_one);
    }
    // softmax + AV
    {
        dim3 grid(D_DIM / 128, B_DIM);                       // 128 blocks
        softmax_av_kernel<<<grid, 256>>>(context, out_ctx, out_attn);
    }
}

// round 8
// speedup vs baseline: 2.5257x; 1.2183x over previous
#include <cuda_runtime.h>
#include <math.h>

#define T_DIM 32
#define B_DIM 16
#define S_DIM 128
#define D_DIM 1024

// Scratch (device globals: allocation-free per harness rules)
__device__ float g_pi[T_DIM * B_DIM * D_DIM];      // 2 MB  [T,B,D]
__device__ float g_pc[B_DIM * S_DIM * D_DIM];      // 8 MB  [B,S,D]
__device__ float g_scores[T_DIM * B_DIM * S_DIM];  // 256 KB [T,B,S]

// ===========================================================================
// Tensor-core GEMM (NT): C[m,n] = sum_k A[m,k]*W[n,k] + bias[n]
// mma.sync.m16n8k8 tf32, 2-term split: A = Ah + Al (exact), B ~= Bh (rounded).
// C ≈ Ah·Bh + Al·Bh = A·Bh; dropped A·Bl ⇒ ~2.4e-4 rel on pi/pc (OK vs 1e-3).
// Block tile 64x64, BK=32, 128 threads (4 warps, each 32x32), cp.async
// 2-stage pipeline. Blocks [0,128): pi (M=512). Blocks [128,640): pc (M=2048).
// ===========================================================================
#define GBM 64
#define GBN 64
#define GBK 32
#define GKPAD 36                 // 32 + 4 floats: 16B-aligned rows, no LDS conflicts
#define PI_BLOCKS 128            // (512/64) * (1024/64)
#define PC_BLOCKS 512            // (2048/64) * (1024/64)
#define NKT (D_DIM / GBK)        // 32 k-tiles

__device__ __forceinline__ void cp16(void* smem, const void* g) {
    unsigned saddr = (unsigned)__cvta_generic_to_shared(smem);
    asm volatile("cp.async.cg.shared.global [%0], [%1], 16;" :: "r"(saddr), "l"(g));
}
__device__ __forceinline__ void split_tf32(float f, unsigned& hi, unsigned& lo) {
    asm("cvt.rna.tf32.f32 %0, %1;" : "=r"(hi) : "f"(f));
    float r = f - __uint_as_float(hi);
    asm("cvt.rna.tf32.f32 %0, %1;" : "=r"(lo) : "f"(r));
}
__device__ __forceinline__ unsigned round_tf32(float f) {
    unsigned h;
    asm("cvt.rna.tf32.f32 %0, %1;" : "=r"(h) : "f"(f));
    return h;
}
__device__ __forceinline__ void mma_tf32(float c[4], const unsigned a[4], const unsigned b[2]) {
    asm volatile(
        "mma.sync.aligned.m16n8k8.row.col.f32.tf32.tf32.f32 "
        "{%0,%1,%2,%3}, {%4,%5,%6,%7}, {%8,%9}, {%0,%1,%2,%3};"
        : "+f"(c[0]), "+f"(c[1]), "+f"(c[2]), "+f"(c[3])
        : "r"(a[0]), "r"(a[1]), "r"(a[2]), "r"(a[3]), "r"(b[0]), "r"(b[1]));
}

__global__ __launch_bounds__(128, 5)
void gemm_tc(const float* __restrict__ inputs, const float* __restrict__ W_in,
             const float* __restrict__ b_in,
             const float* __restrict__ context, const float* __restrict__ W_ctx,
             const float* __restrict__ b_ctx)
{
    __shared__ __align__(16) float As[2][GBM][GKPAD];
    __shared__ __align__(16) float Bs[2][GBN][GKPAD];

    const int bid = blockIdx.x;
    const float* A; const float* W; const float* bias; float* C;
    int bm, bn;
    if (bid < PI_BLOCKS) {
        A = inputs;  W = W_in;  bias = b_in;  C = g_pi;
        bm = (bid >> 4) * GBM;  bn = (bid & 15) * GBN;
    } else {
        const int b2 = bid - PI_BLOCKS;
        A = context; W = W_ctx; bias = b_ctx; C = g_pc;
        bm = (b2 >> 4) * GBM;   bn = (b2 & 15) * GBN;
    }
    const int K = D_DIM, N = D_DIM;

    const int tid  = threadIdx.x;          // 128
    const int wid  = tid >> 5;             // 0..3
    const int lane = tid & 31;
    const int warp_m = (wid & 1) * 32;
    const int warp_n = (wid >> 1) * 32;
    const int lr = lane >> 2;              // 0..7
    const int lc = lane & 3;               // 0..3

    float acc[2][4][4];
    #pragma unroll
    for (int i = 0; i < 2; i++)
        #pragma unroll
        for (int j = 0; j < 4; j++)
            #pragma unroll
            for (int q = 0; q < 4; q++) acc[i][j][q] = 0.f;

    // --- async tile loader: 512 16B chunks per operand, 4 per thread each ---
    auto issue = [&](int kt, int buf) {
        const int k0 = kt * GBK;
        #pragma unroll
        for (int i = 0; i < 4; i++) {
            int id  = tid + i * 128;       // 0..511
            int row = id >> 3;             // 0..63
            int c4  = (id & 7) * 4;        // float offset, 16B chunks
            cp16(&As[buf][row][c4], A + (size_t)(bm + row) * K + k0 + c4);
            cp16(&Bs[buf][row][c4], W + (size_t)(bn + row) * K + k0 + c4);
        }
        asm volatile("cp.async.commit_group;");
    };

    issue(0, 0);
    issue(1, 1);

    for (int kt = 0; kt < NKT; kt++) {
        if (kt < NKT - 1) asm volatile("cp.async.wait_group 1;");
        else              asm volatile("cp.async.wait_group 0;");
        __syncthreads();

        const int st = kt & 1;
        #pragma unroll
        for (int ka = 0; ka < 4; ka++) {
            const int k8 = ka * 8;
            // A fragments (2 m-atoms), split hi/lo (exact 2-term repr.)
            unsigned ah[2][4], al[2][4];
            #pragma unroll
            for (int i = 0; i < 2; i++) {
                int r = warp_m + i * 16 + lr;
                split_tf32(As[st][r][k8 + lc],         ah[i][0], al[i][0]);
                split_tf32(As[st][r + 8][k8 + lc],     ah[i][1], al[i][1]);
                split_tf32(As[st][r][k8 + lc + 4],     ah[i][2], al[i][2]);
                split_tf32(As[st][r + 8][k8 + lc + 4], ah[i][3], al[i][3]);
            }
            // B fragments (4 n-atoms), rounded once
            unsigned bh[4][2];
            #pragma unroll
            for (int j = 0; j < 4; j++) {
                int n = warp_n + j * 8 + lr;
                bh[j][0] = round_tf32(Bs[st][n][k8 + lc]);
                bh[j][1] = round_tf32(Bs[st][n][k8 + lc + 4]);
            }
            #pragma unroll
            for (int i = 0; i < 2; i++)
                #pragma unroll
                for (int j = 0; j < 4; j++) {
                    mma_tf32(acc[i][j], ah[i], bh[j]);   // A_hi * B
                    mma_tf32(acc[i][j], al[i], bh[j]);   // A_lo * B
                }
        }
        __syncthreads();
        if (kt + 2 < NKT) issue(kt + 2, st);
    }

    // Epilogue: c0/c1 at (row, 2c),(row, 2c+1); c2/c3 at row+8. float2 stores.
    #pragma unroll
    for (int i = 0; i < 2; i++) {
        int r0 = bm + warp_m + i * 16 + lr;
        #pragma unroll
        for (int j = 0; j < 4; j++) {
            int c0 = bn + warp_n + j * 8 + 2 * lc;
            float2 bv = *(const float2*)(bias + c0);
            float2 o0 = make_float2(acc[i][j][0] + bv.x, acc[i][j][1] + bv.y);
            float2 o1 = make_float2(acc[i][j][2] + bv.x, acc[i][j][3] + bv.y);
            *(float2*)(C + (size_t)r0 * N + c0)       = o0;
            *(float2*)(C + (size_t)(r0 + 8) * N + c0) = o1;
        }
    }
}

// ---------------------------------------------------------------------------
// scores[t,b,s] = sum_d swish(pi[t,b,d] + pc[b,s,d]) * w_one[d]
// sigmoid via MUFU.TANH: sigmoid(x) = 0.5*tanh(x/2) + 0.5  (1 MUFU vs 2)
// ---------------------------------------------------------------------------
#define TT 16
#define SB 32
#define DC 128

__device__ __forceinline__ float fast_sigmoid(float x) {
    float h = 0.5f * x, t;
    asm("tanh.approx.f32 %0, %1;" : "=f"(t) : "f"(h));
    return fmaf(0.5f, t, 0.5f);
}

__global__ __launch_bounds__(256)
void scores_kernel(const float* __restrict__ w_one)
{
    __shared__ float sp[TT][DC + 1];
    __shared__ float sc[SB][DC + 1];
    __shared__ float sw[DC];

    const int b   = blockIdx.z;
    const int t0  = blockIdx.y * TT;
    const int s0  = blockIdx.x * SB;
    const int tid = threadIdx.x;
    const int tl  = tid >> 4;
    const int sl  = tid & 15;

    float acc0 = 0.f, acc1 = 0.f;

    for (int d0 = 0; d0 < D_DIM; d0 += DC) {
        #pragma unroll
        for (int i = 0; i < 2; i++) {
            int l = tid + i * 256;
            int row = l >> 5;
            int c = (l & 31) << 2;
            float4 v = *(const float4*)(g_pi +
                ((size_t)(t0 + row) * B_DIM + b) * D_DIM + d0 + c);
            sp[row][c] = v.x; sp[row][c + 1] = v.y;
            sp[row][c + 2] = v.z; sp[row][c + 3] = v.w;
        }
        #pragma unroll
        for (int i = 0; i < 4; i++) {
            int l = tid + i * 256;
            int row = l >> 5;
            int c = (l & 31) << 2;
            float4 v = *(const float4*)(g_pc +
                ((size_t)b * S_DIM + s0 + row) * D_DIM + d0 + c);
            sc[row][c] = v.x; sc[row][c + 1] = v.y;
            sc[row][c + 2] = v.z; sc[row][c + 3] = v.w;
        }
        if (tid < DC) sw[tid] = w_one[d0 + tid];
        __syncthreads();

        #pragma unroll 8
        for (int k = 0; k < DC; k++) {
            float w = sw[k];
            float p = sp[tl][k];
            float x0 = p + sc[sl][k];
            float x1 = p + sc[sl + 16][k];
            acc0 = fmaf(w * x0, fast_sigmoid(x0), acc0);
            acc1 = fmaf(w * x1, fast_sigmoid(x1), acc1);
        }
        __syncthreads();
    }

    g_scores[((size_t)(t0 + tl) * B_DIM + b) * S_DIM + s0 + sl]      = acc0;
    g_scores[((size_t)(t0 + tl) * B_DIM + b) * S_DIM + s0 + sl + 16] = acc1;
}

// ---------------------------------------------------------------------------
// Softmax over s + attn_context[t,b,d] = sum_s attn[t,b,s] * context[b,s,d]
// ---------------------------------------------------------------------------
__global__ __launch_bounds__(256)
void softmax_av_kernel(const float* __restrict__ context,
                       float* __restrict__ out_ctx,
                       float* __restrict__ out_attn)
{
    __shared__ float sat[T_DIM][S_DIM];
    __shared__ float sctx[64][128];

    const int dc  = blockIdx.x;
    const int b   = blockIdx.y;
    const int tid = threadIdx.x;

    #pragma unroll
    for (int i = 0; i < 16; i++) {
        int l = tid + i * 256;
        int t = l >> 7;
        int s = l & 127;
        sat[t][s] = g_scores[((size_t)t * B_DIM + b) * S_DIM + s];
    }
    __syncthreads();

    {
        int t = tid >> 3;
        int part = tid & 7;
        int sbase = part * 16;
        float m = -1e30f;
        #pragma unroll
        for (int i = 0; i < 16; i++) m = fmaxf(m, sat[t][sbase + i]);
        #pragma unroll
        for (int o = 4; o > 0; o >>= 1)
            m = fmaxf(m, __shfl_xor_sync(0xffffffffu, m, o, 8));
        float e[16];
        float sum = 0.f;
        #pragma unroll
        for (int i = 0; i < 16; i++) {
            e[i] = __expf(sat[t][sbase + i] - m);
            sum += e[i];
        }
        #pragma unroll
        for (int o = 4; o > 0; o >>= 1)
            sum += __shfl_xor_sync(0xffffffffu, sum, o, 8);
        float inv = __fdividef(1.f, sum);
        #pragma unroll
        for (int i = 0; i < 16; i++) sat[t][sbase + i] = e[i] * inv;
    }
    __syncthreads();

    if (dc == 0) {
        int t = tid >> 3;
        int sbase = (tid & 7) * 16;
        #pragma unroll
        for (int i = 0; i < 16; i++)
            out_attn[((size_t)t * B_DIM + b) * S_DIM + sbase + i] = sat[t][sbase + i];
    }

    const int t2 = tid >> 7;
    const int dl = tid & 127;
    float acc[16];
    #pragma unroll
    for (int i = 0; i < 16; i++) acc[i] = 0.f;

    for (int sc0 = 0; sc0 < S_DIM; sc0 += 64) {
        __syncthreads();
        #pragma unroll
        for (int i = 0; i < 8; i++) {
            int l = tid + i * 256;
            int row = l >> 5;
            int c = (l & 31) << 2;
            float4 v = *(const float4*)(context +
                ((size_t)b * S_DIM + sc0 + row) * D_DIM + dc * 128 + c);
            sctx[row][c] = v.x; sctx[row][c + 1] = v.y;
            sctx[row][c + 2] = v.z; sctx[row][c + 3] = v.w;
        }
        __syncthreads();

        for (int s = 0; s < 64; s++) {
            float cv = sctx[s][dl];
            #pragma unroll
            for (int i = 0; i < 16; i++)
                acc[i] = fmaf(sat[i * 2 + t2][sc0 + s], cv, acc[i]);
        }
    }

    #pragma unroll
    for (int i = 0; i < 16; i++) {
        out_ctx[((size_t)(i * 2 + t2) * B_DIM + b) * D_DIM + dc * 128 + dl] = acc[i];
    }
}

// ---------------------------------------------------------------------------
// Launch.  b_one skipped (softmax shift-invariant; scores not an output).
// ---------------------------------------------------------------------------
extern "C" void kernel_launch(void* const* d_in, const int* in_sizes, int n_in,
                              void* d_out, int out_size)
{
    const float* inputs  = (const float*)d_in[0];
    const float* context = (const float*)d_in[1];
    const float* W_in    = (const float*)d_in[2];
    const float* b_in    = (const float*)d_in[3];
    const float* W_ctx   = (const float*)d_in[4];
    const float* b_ctx   = (const float*)d_in[5];
    const float* w_one   = (const float*)d_in[6];

    float* out      = (float*)d_out;
    float* out_ctx  = out;                                   // [T,B,D]
    float* out_attn = out + (size_t)T_DIM * B_DIM * D_DIM;   // [T,B,S]

    // Fused pi + pc tensor-core GEMMs: 128 + 512 = 640 blocks
    gemm_tc<<<PI_BLOCKS + PC_BLOCKS, 128>>>(inputs, W_in, b_in,
                                            context, W_ctx, b_ctx);
    // scores
    {
        dim3 grid(S_DIM / SB, T_DIM / TT, B_DIM);            // 128 blocks
        scores_kernel<<<grid, 256>>>(w_one);
    }
    // softmax + AV
    {
        dim3 grid(D_DIM / 128, B_DIM);                       // 128 blocks
        softmax_av_kernel<<<grid, 256>>>(context, out_ctx, out_attn);
    }
}